// round 10
// baseline (speedup 1.0000x reference)
#include <cuda_runtime.h>
#include <cstdint>

// Involution2d on GB300 (sm_103 base ISA). B=4, C=256, H=W=64, G=16, K=7, PAD=3.
// R10: split gemm (mma.sync tf32, triple-buffered) / apply (fp32 conv) kernels.
// Grid for both: (b*hpair=128, gqp=8). kern scratch lives in L2 (51 MB).

#define CH 256
#define HH 64
#define WW 64
#define KT 7
#define KK 49
#define CC 32                  // channels per chunk
#define NCHUNK 8
#define TAPS 112               // 2 groups * 56 padded taps
#define PX 128                 // pixels per block (2 rows)
#define KROW 132               // k_s row stride, 132%32=4 -> conflict-free
#define NSLOT 98               // 2 groups * 49 valid taps

#define XBUF_F (CC * PX)       // 4096 floats
#define WBUF_F (CC * TAPS)     // 3584 floats
#define GEMM_SMEM (3 * (XBUF_F + WBUF_F) * 4)   // 92160 B (k_s aliases: 98*132*4=51744)
#define APPLY_SMEM (NSLOT * KROW * 4)           // 51744 B

// g_wt2: [cgOctet 32][gqp 8][n 112][8], 8 = (unit<<1)|half with
//   unit = (k8 & 3) ^ ((n >> 2) & 3), half = k8 >> 2, k8 = channel & 7
__device__ float g_wt2[32 * 8 * TAPS * 8];
// kern scratch: [blk 1024][slot 98][px 128]
__device__ float g_kern2[(size_t)1024 * NSLOT * 128];

// ---------------- helpers ----------------
__device__ __forceinline__ uint32_t f2tf32u(float x) {
    uint32_t u;
    asm("cvt.rn.tf32.f32 %0, %1;" : "=r"(u) : "f"(x));
    return u;
}
__device__ __forceinline__ void cp16(float* dst, const float* src) {
    unsigned sa = (unsigned)__cvta_generic_to_shared(dst);
    asm volatile("cp.async.cg.shared.global [%0], [%1], 16;" :: "r"(sa), "l"(src));
}
__device__ __forceinline__ void cp_commit() { asm volatile("cp.async.commit_group;"); }
__device__ __forceinline__ void cp_wait1()  { asm volatile("cp.async.wait_group 1;"); }
__device__ __forceinline__ void cp_wait0()  { asm volatile("cp.async.wait_group 0;"); }

__device__ __forceinline__ void mma8(float* c, const uint32_t* a, const uint32_t* b) {
    asm volatile(
        "mma.sync.aligned.m16n8k8.row.col.f32.tf32.tf32.f32 "
        "{%0,%1,%2,%3}, {%4,%5,%6,%7}, {%8,%9}, {%0,%1,%2,%3};"
        : "+f"(c[0]), "+f"(c[1]), "+f"(c[2]), "+f"(c[3])
        : "r"(a[0]), "r"(a[1]), "r"(a[2]), "r"(a[3]), "r"(b[0]), "r"(b[1]));
}

// ---------------- w repack (unchanged from R9) ----------------
__global__ void wt_pack_kernel(const float* __restrict__ wk) {
    const int blk = blockIdx.x;
    const int cgO = blk >> 3, gqp = blk & 7;
    const int n = threadIdx.x;              // 0..111
    const int grp = n / 56, kk = n % 56;
    const int c0 = cgO * 8;
    float* dst = g_wt2 + ((size_t)blk * TAPS + n) * 8;
    if (kk < KK) {
        const float* src = wk + (size_t)((gqp * 2 + grp) * KK + kk) * CH + c0;
        #pragma unroll
        for (int k8 = 0; k8 < 8; ++k8) {
            const int unit = (k8 & 3) ^ ((n >> 2) & 3);
            const int half = k8 >> 2;
            dst[unit * 2 + half] = __uint_as_float(f2tf32u(src[k8]));
        }
    } else {
        #pragma unroll
        for (int i = 0; i < 8; ++i) dst[i] = 0.0f;
    }
}

// ---------------- GEMM kernel: kern = X * W^T + bias ----------------
__global__ __launch_bounds__(256, 2)
void gemm_kernel(const float* __restrict__ x, const float* __restrict__ bk) {
    extern __shared__ float sm[];
    float* k_s = sm;                         // aliases buffers after mainloop

    const int t   = threadIdx.x;
    const int rb  = blockIdx.x;
    const int b   = rb >> 5;
    const int h   = (rb & 31) * 2;
    const int gqp = blockIdx.y;
    const int blk = rb * 8 + gqp;

    // buffer bases: x0,x1,x2 then w0,w1,w2
    auto xbuf = [&](int i) { return sm + i * XBUF_F; };
    auto wbuf = [&](int i) { return sm + 3 * XBUF_F + i * WBUF_F; };

    auto load_chunk = [&](int chunk, int bi) {
        const int c0 = chunk * CC;
        float* xb = xbuf(bi);
        float* wb = wbuf(bi);
        #pragma unroll
        for (int i = 0; i < 4; ++i) {                 // 1024 cp16
            const int u = t + 256 * i;
            const int k = u >> 5;
            const int p4 = (u & 31) << 2;
            cp16(xb + k * PX + (p4 ^ (8 * (k & 3))),
                 x + ((size_t)(b * CH + c0 + k)) * 4096 + h * 64 + p4);
        }
        #pragma unroll
        for (int i = 0; i < 4; ++i) {                 // 896 cp16
            const int u = t + 256 * i;
            if (u < 896) {
                const int cg = u / 224;
                const int r = u - cg * 224;
                cp16(wb + cg * (TAPS * 8) + r * 4,
                     g_wt2 + ((size_t)((chunk * 4 + cg) * 8 + gqp) * TAPS) * 8 + r * 4);
            }
        }
        cp_commit();
    };

    const int wid = t >> 5, lane = t & 31;
    const int la = lane & 3, gid = lane >> 2;
    const int mq = wid & 3, nq = wid >> 2;
    const int m0w = mq * 32;
    const int n0w = nq * 56;
    const int sw = 8 * la;

    float acc[2][7][4];
    #pragma unroll
    for (int mt = 0; mt < 2; ++mt)
        #pragma unroll
        for (int nt = 0; nt < 7; ++nt)
            #pragma unroll
            for (int i = 0; i < 4; ++i) acc[mt][nt][i] = 0.0f;

    load_chunk(0, 0);
    load_chunk(1, 1);

    for (int ch = 0; ch < NCHUNK; ++ch) {
        if (ch < NCHUNK - 1) cp_wait1(); else cp_wait0();
        __syncthreads();                       // all threads' chunk-ch copies done,
                                               // all finished MMA(ch-1)
        if (ch + 2 < NCHUNK) load_chunk(ch + 2, (ch + 2) % 3);

        const float* xb = xbuf(ch % 3);
        const float* wb = wbuf(ch % 3);

        #pragma unroll
        for (int ks = 0; ks < 4; ++ks) {
            const int kb = ks * 8;
            uint32_t af[2][4];
            #pragma unroll
            for (int mt = 0; mt < 2; ++mt) {
                const int rm = m0w + mt * 16;
                const int r0 = (rm + gid) ^ sw;
                const int r1 = (rm + 8 + gid) ^ sw;
                af[mt][0] = f2tf32u(xb[(kb + la) * PX + r0]);
                af[mt][1] = f2tf32u(xb[(kb + la) * PX + r1]);
                af[mt][2] = f2tf32u(xb[(kb + la + 4) * PX + r0]);
                af[mt][3] = f2tf32u(xb[(kb + la + 4) * PX + r1]);
            }
            const float* wrow = wb + ks * (TAPS * 8);
            #pragma unroll
            for (int nt = 0; nt < 7; ++nt) {
                const int cn = n0w + nt * 8 + gid;
                const int unit = la ^ ((cn >> 2) & 3);
                const float2 bv = *(const float2*)(wrow + cn * 8 + unit * 2);
                uint32_t bf[2] = {__float_as_uint(bv.x), __float_as_uint(bv.y)};
                mma8(acc[0][nt], af[0], bf);
                mma8(acc[1][nt], af[1], bf);
            }
        }
    }
    __syncthreads();                           // all MMAs done before k_s alias

    // ---- epilogue: bias add -> k_s[slot][px] (STS), then coalesced STG ----
    {
        const int px0 = m0w + gid;
        #pragma unroll
        for (int nt = 0; nt < 7; ++nt) {
            const int kk = nt * 8 + la * 2;
            if (kk < KK) {
                const float bias = bk[(gqp * 2 + nq) * KK + kk];
                const int s = nq * KK + kk;
                k_s[s * KROW + px0]      = acc[0][nt][0] + bias;
                k_s[s * KROW + px0 + 8]  = acc[0][nt][2] + bias;
                k_s[s * KROW + px0 + 16] = acc[1][nt][0] + bias;
                k_s[s * KROW + px0 + 24] = acc[1][nt][2] + bias;
            }
            if (kk + 1 < KK) {
                const float bias1 = bk[(gqp * 2 + nq) * KK + kk + 1];
                const int s1 = nq * KK + kk + 1;
                k_s[s1 * KROW + px0]      = acc[0][nt][1] + bias1;
                k_s[s1 * KROW + px0 + 8]  = acc[0][nt][3] + bias1;
                k_s[s1 * KROW + px0 + 16] = acc[1][nt][1] + bias1;
                k_s[s1 * KROW + px0 + 24] = acc[1][nt][3] + bias1;
            }
        }
    }
    __syncthreads();

    // coalesced write-out: 98 slots x 128 px
    float* kout = g_kern2 + (size_t)blk * NSLOT * 128;
    #pragma unroll
    for (int i = 0; i < 13; ++i) {
        const int u = t + 256 * i;             // float4 units, 3136 total
        if (u < NSLOT * 32) {
            const int slot = u >> 5;
            const int p4 = (u & 31) << 2;
            const float4 v = *(const float4*)&k_s[slot * KROW + p4];
            *(float4*)(kout + slot * 128 + p4) = v;
        }
    }
}

// ---------------- apply kernel: 49-tap dynamic conv (fp32) ----------------
__global__ __launch_bounds__(256, 3)
void apply_kernel(const float* __restrict__ x, float* __restrict__ out) {
    extern __shared__ float k_s[];             // [slot 98][KROW]

    const int t   = threadIdx.x;
    const int rb  = blockIdx.x;
    const int b   = rb >> 5;
    const int h   = (rb & 31) * 2;
    const int gqp = blockIdx.y;
    const int blk = rb * 8 + gqp;

    // load kern tile via cp.async, coalesced
    const float* kin = g_kern2 + (size_t)blk * NSLOT * 128;
    #pragma unroll
    for (int i = 0; i < 13; ++i) {
        const int u = t + 256 * i;
        if (u < NSLOT * 32) {
            const int slot = u >> 5;
            const int p4 = (u & 31) << 2;
            cp16(&k_s[slot * KROW + p4], kin + slot * 128 + p4);
        }
    }
    cp_commit();
    cp_wait0();
    __syncthreads();

    const int pxg  = t & 15, w0 = pxg << 2;
    const int chq  = (t >> 4) & 3;
    const int grp2 = (t >> 6) & 1;
    const int hrow = t >> 7;
    const int hout = h + hrow;

    float o[4][4];
    #pragma unroll
    for (int m = 0; m < 4; ++m)
        #pragma unroll
        for (int pi = 0; pi < 4; ++pi) o[m][pi] = 0.0f;

    #pragma unroll
    for (int kh = 0; kh < KT; ++kh) {
        const int hh = hout + kh - 3;
        if ((unsigned)hh >= (unsigned)HH) continue;

        float4 kvf[KT];
        #pragma unroll
        for (int kw = 0; kw < KT; ++kw)
            kvf[kw] = *(const float4*)&k_s[(grp2 * KK + kh * KT + kw) * KROW + hrow * 64 + w0];

        #pragma unroll
        for (int m = 0; m < 4; ++m) {
            const int c = gqp * 32 + grp2 * 16 + chq + (m << 2);
            const float* xr = x + ((size_t)(b * CH + c) * HH + hh) * WW;
            const float4 A = (pxg >= 1)  ? *(const float4*)(xr + w0 - 4)
                                         : make_float4(0.f, 0.f, 0.f, 0.f);
            const float4 Bv = *(const float4*)(xr + w0);
            const float4 Cc = (pxg <= 14) ? *(const float4*)(xr + w0 + 4)
                                          : make_float4(0.f, 0.f, 0.f, 0.f);
            const float xv[10] = {A.y, A.z, A.w, Bv.x, Bv.y, Bv.z, Bv.w, Cc.x, Cc.y, Cc.z};
            #pragma unroll
            for (int kw = 0; kw < KT; ++kw) {
                o[m][0] += xv[kw]     * kvf[kw].x;
                o[m][1] += xv[kw + 1] * kvf[kw].y;
                o[m][2] += xv[kw + 2] * kvf[kw].z;
                o[m][3] += xv[kw + 3] * kvf[kw].w;
            }
        }
    }

    #pragma unroll
    for (int m = 0; m < 4; ++m) {
        const int c = gqp * 32 + grp2 * 16 + chq + (m << 2);
        *reinterpret_cast<float4*>(out + ((size_t)(b * CH + c) * HH + hout) * WW + w0) =
            make_float4(o[m][0], o[m][1], o[m][2], o[m][3]);
    }
}

extern "C" void kernel_launch(void* const* d_in, const int* in_sizes, int n_in,
                              void* d_out, int out_size) {
    const float* x  = (const float*)d_in[0];
    const float* wk = (const float*)d_in[1];
    const float* bk = (const float*)d_in[2];
    float* out      = (float*)d_out;

    wt_pack_kernel<<<256, TAPS>>>(wk);

    cudaFuncSetAttribute(gemm_kernel,
                         cudaFuncAttributeMaxDynamicSharedMemorySize, GEMM_SMEM);
    dim3 grid(4 * 32, 8);
    gemm_kernel<<<grid, 256, GEMM_SMEM>>>(x, bk);

    cudaFuncSetAttribute(apply_kernel,
                         cudaFuncAttributeMaxDynamicSharedMemorySize, APPLY_SMEM);
    apply_kernel<<<grid, 256, APPLY_SMEM>>>(x, out);
}